// round 1
// baseline (speedup 1.0000x reference)
#include <cuda_runtime.h>
#include <cstdint>
#include <math.h>

// ---------------------------------------------------------------------------
// Problem constants
// ---------------------------------------------------------------------------
constexpr int B_  = 4;
constexpr int L_  = 2048;
constexpr int D_  = 512;
constexpr int H_  = 1024;   // 2*D
constexpr int R_  = 32;
constexpr int S_  = 16;
constexpr int M_  = B_ * L_;        // 8192 tokens
constexpr int H2_ = 2 * H_;         // 2048

// ---------------------------------------------------------------------------
// Scratch (device globals; no allocation allowed)
// ---------------------------------------------------------------------------
__device__ float g_cln[M_ * D_];     // layernorm(ctx)
__device__ float g_z  [M_ * H2_];    // x @ Wa^T + ba
__device__ float g_p  [M_ * H_];     // cln @ Wgb^T + bgb
__device__ float g_q  [M_ * H_];     // cln @ Wgc^T + bgc
__device__ float g_u  [M_ * H_];     // gated u (pre-conv)
__device__ float g_v  [M_ * H_];     // gated v
__device__ float g_uc [M_ * H_];     // silu(conv(u))
__device__ float g_zc [M_ * 64];     // uc @ Wc^T   (R + 2S = 64)
__device__ float g_dt [M_ * H_];     // softplus(zc[:, :R] @ We^T + be)
__device__ float g_yv [M_ * H_];     // (scan_y + uc*g) * silu(v)

// ---------------------------------------------------------------------------
// LayerNorm over D=512, one block (256 threads) per token
// ---------------------------------------------------------------------------
__global__ void ln_kernel(const float* __restrict__ ctx,
                          const float* __restrict__ w,
                          const float* __restrict__ b,
                          float* __restrict__ out)
{
    __shared__ float red[32];
    const int m = blockIdx.x;
    const int t = threadIdx.x;
    const float* xr = ctx + (size_t)m * D_;
    float v0 = xr[t], v1 = xr[t + 256];

    float s = v0 + v1;
    #pragma unroll
    for (int o = 16; o; o >>= 1) s += __shfl_xor_sync(0xffffffffu, s, o);
    if ((t & 31) == 0) red[t >> 5] = s;
    __syncthreads();
    if (t < 32) {
        float r = (t < 8) ? red[t] : 0.f;
        #pragma unroll
        for (int o = 4; o; o >>= 1) r += __shfl_xor_sync(0xffffffffu, r, o);
        if (t == 0) red[0] = r;
    }
    __syncthreads();
    const float mu = red[0] * (1.f / D_);
    const float d0 = v0 - mu, d1 = v1 - mu;

    float sq = d0 * d0 + d1 * d1;
    #pragma unroll
    for (int o = 16; o; o >>= 1) sq += __shfl_xor_sync(0xffffffffu, sq, o);
    __syncthreads();                       // everyone done reading red[0]
    if ((t & 31) == 0) red[t >> 5] = sq;
    __syncthreads();
    if (t < 32) {
        float r = (t < 8) ? red[t] : 0.f;
        #pragma unroll
        for (int o = 4; o; o >>= 1) r += __shfl_xor_sync(0xffffffffu, r, o);
        if (t == 0) red[0] = r;
    }
    __syncthreads();
    const float inv = rsqrtf(red[0] * (1.f / D_) + 1e-5f);

    float* orow = out + (size_t)m * D_;
    orow[t]       = d0 * inv * w[t]       + b[t];
    orow[t + 256] = d1 * inv * w[t + 256] + b[t + 256];
}

// ---------------------------------------------------------------------------
// SGEMM:  C[m,n] = sum_k A[m*lda+k] * W[n*ldw+k]  (+bias, +activation)
// 128x128 tile, BK=8, 256 threads, 8x8 micro-tile.
// Requires M%128==0, N%128==0, K%8==0, all row ptrs 16B aligned.
// ACT: 0 = identity, 1 = softplus
// ---------------------------------------------------------------------------
template<int ACT>
__global__ __launch_bounds__(256)
void gemm128(const float* __restrict__ A, int lda,
             const float* __restrict__ W, int ldw,
             const float* __restrict__ bias,
             float* __restrict__ C, int ldc, int K)
{
    __shared__ float As[8][128];
    __shared__ float Bs[8][128];
    const int tid  = threadIdx.x;
    const int m0   = blockIdx.y * 128;
    const int n0   = blockIdx.x * 128;
    const int lrow = tid >> 1;
    const int lcol = (tid & 1) * 4;
    const float* Ap = A + (size_t)(m0 + lrow) * lda + lcol;
    const float* Wp = W + (size_t)(n0 + lrow) * ldw + lcol;
    const int ty = tid >> 4, tx = tid & 15;

    float acc[8][8];
    #pragma unroll
    for (int i = 0; i < 8; i++)
        #pragma unroll
        for (int j = 0; j < 8; j++) acc[i][j] = 0.f;

    for (int k0 = 0; k0 < K; k0 += 8) {
        const float4 av = *(const float4*)(Ap + k0);
        const float4 wv = *(const float4*)(Wp + k0);
        __syncthreads();
        As[lcol + 0][lrow] = av.x; As[lcol + 1][lrow] = av.y;
        As[lcol + 2][lrow] = av.z; As[lcol + 3][lrow] = av.w;
        Bs[lcol + 0][lrow] = wv.x; Bs[lcol + 1][lrow] = wv.y;
        Bs[lcol + 2][lrow] = wv.z; Bs[lcol + 3][lrow] = wv.w;
        __syncthreads();
        #pragma unroll
        for (int kk = 0; kk < 8; kk++) {
            const float4 a0 = *(const float4*)&As[kk][ty * 8];
            const float4 a1 = *(const float4*)&As[kk][ty * 8 + 4];
            const float4 b0 = *(const float4*)&Bs[kk][tx * 8];
            const float4 b1 = *(const float4*)&Bs[kk][tx * 8 + 4];
            const float am[8] = {a0.x, a0.y, a0.z, a0.w, a1.x, a1.y, a1.z, a1.w};
            const float bn[8] = {b0.x, b0.y, b0.z, b0.w, b1.x, b1.y, b1.z, b1.w};
            #pragma unroll
            for (int i = 0; i < 8; i++)
                #pragma unroll
                for (int j = 0; j < 8; j++)
                    acc[i][j] = fmaf(am[i], bn[j], acc[i][j]);
        }
    }

    #pragma unroll
    for (int i = 0; i < 8; i++) {
        const int m = m0 + ty * 8 + i;
        float* crow = C + (size_t)m * ldc + n0 + tx * 8;
        #pragma unroll
        for (int j = 0; j < 8; j += 4) {
            float rr[4];
            #pragma unroll
            for (int qq = 0; qq < 4; qq++) {
                float val = acc[i][j + qq];
                if (bias) val += bias[n0 + tx * 8 + j + qq];
                if (ACT == 1)
                    val = (val > 20.f) ? val : log1pf(__expf(val));
                rr[qq] = val;
            }
            float4 r; r.x = rr[0]; r.y = rr[1]; r.z = rr[2]; r.w = rr[3];
            *(float4*)(crow + j) = r;
        }
    }
}

// ---------------------------------------------------------------------------
// SGEMM 64x64 tile, BK=16, 256 threads, 4x4 micro-tile (for N=64 zc GEMM).
// ---------------------------------------------------------------------------
__global__ __launch_bounds__(256)
void gemm64(const float* __restrict__ A, int lda,
            const float* __restrict__ W, int ldw,
            float* __restrict__ C, int ldc, int K)
{
    __shared__ float As[16][64];
    __shared__ float Bs[16][64];
    const int tid  = threadIdx.x;
    const int m0   = blockIdx.y * 64;
    const int n0   = blockIdx.x * 64;
    const int lrow = tid >> 2;
    const int lcol = (tid & 3) * 4;
    const float* Ap = A + (size_t)(m0 + lrow) * lda + lcol;
    const float* Wp = W + (size_t)(n0 + lrow) * ldw + lcol;
    const int ty = tid >> 4, tx = tid & 15;

    float acc[4][4];
    #pragma unroll
    for (int i = 0; i < 4; i++)
        #pragma unroll
        for (int j = 0; j < 4; j++) acc[i][j] = 0.f;

    for (int k0 = 0; k0 < K; k0 += 16) {
        const float4 av = *(const float4*)(Ap + k0);
        const float4 wv = *(const float4*)(Wp + k0);
        __syncthreads();
        As[lcol + 0][lrow] = av.x; As[lcol + 1][lrow] = av.y;
        As[lcol + 2][lrow] = av.z; As[lcol + 3][lrow] = av.w;
        Bs[lcol + 0][lrow] = wv.x; Bs[lcol + 1][lrow] = wv.y;
        Bs[lcol + 2][lrow] = wv.z; Bs[lcol + 3][lrow] = wv.w;
        __syncthreads();
        #pragma unroll
        for (int kk = 0; kk < 16; kk++) {
            const float4 a = *(const float4*)&As[kk][ty * 4];
            const float4 b = *(const float4*)&Bs[kk][tx * 4];
            const float am[4] = {a.x, a.y, a.z, a.w};
            const float bn[4] = {b.x, b.y, b.z, b.w};
            #pragma unroll
            for (int i = 0; i < 4; i++)
                #pragma unroll
                for (int j = 0; j < 4; j++)
                    acc[i][j] = fmaf(am[i], bn[j], acc[i][j]);
        }
    }

    #pragma unroll
    for (int i = 0; i < 4; i++) {
        const int m = m0 + ty * 4 + i;
        float4 r; r.x = acc[i][0]; r.y = acc[i][1]; r.z = acc[i][2]; r.w = acc[i][3];
        *(float4*)(C + (size_t)m * ldc + n0 + tx * 4) = r;
    }
}

// ---------------------------------------------------------------------------
// Elementwise gating:  u = z1*(1+sigmoid(p)),  v = z2 + q
// (biases already folded into the GEMM epilogues)
// ---------------------------------------------------------------------------
__global__ void uv_kernel(const float* __restrict__ Z,
                          const float* __restrict__ P,
                          const float* __restrict__ Q,
                          float* __restrict__ u, float* __restrict__ v)
{
    const size_t idx = (size_t)blockIdx.x * blockDim.x + threadIdx.x;
    if (idx >= (size_t)M_ * H_) return;
    const int    h = (int)(idx % H_);
    const size_t m = idx / H_;
    const float z1 = Z[m * H2_ + h];
    const float z2 = Z[m * H2_ + H_ + h];
    const float pv = P[idx];
    const float qv = Q[idx];
    const float sig = 1.f / (1.f + __expf(-pv));
    u[idx] = z1 * (1.f + sig);
    v[idx] = z2 + qv;
}

// ---------------------------------------------------------------------------
// Causal depthwise conv3 + SiLU
// ---------------------------------------------------------------------------
__global__ void conv_kernel(const float* __restrict__ u,
                            const float* __restrict__ cw,
                            const float* __restrict__ cb,
                            float* __restrict__ uc)
{
    const size_t idx = (size_t)blockIdx.x * blockDim.x + threadIdx.x;
    if (idx >= (size_t)M_ * H_) return;
    const int    h = (int)(idx % H_);
    const size_t m = idx / H_;
    const int    l = (int)(m % L_);
    const float x0  = u[idx];
    const float xm1 = (l >= 1) ? u[idx - H_]     : 0.f;
    const float xm2 = (l >= 2) ? u[idx - 2 * H_] : 0.f;
    const float r = cw[h * 3 + 0] * xm2 + cw[h * 3 + 1] * xm1
                  + cw[h * 3 + 2] * x0  + cb[h];
    uc[idx] = r / (1.f + __expf(-r));           // silu
}

// ---------------------------------------------------------------------------
// Selective scan. One warp handles 2 heads for one batch:
//   lanes  0..15 : head h0, states s=0..15
//   lanes 16..31 : head h0+1, states s=0..15
// b_mat/c_mat loaded coalesced (32 lanes = zc cols 32..63), shfl-broadcast.
// Per-step y = sum_s x_s*c_s via 4 xor-shuffles within each 16-lane group.
// Output fused with skip + silu(v):  yv = (y + uc*g) * silu(v).
// ---------------------------------------------------------------------------
__global__ void scan_kernel(const float* __restrict__ uc,
                            const float* __restrict__ dt,
                            const float* __restrict__ zc,
                            const float* __restrict__ v,
                            const float* __restrict__ f_log,
                            const float* __restrict__ g,
                            float* __restrict__ yv)
{
    const int wid  = (int)((blockIdx.x * blockDim.x + threadIdx.x) >> 5);
    const int lane = threadIdx.x & 31;
    if (wid >= B_ * H_ / 2) return;
    const int b  = wid / (H_ / 2);
    const int h0 = (wid % (H_ / 2)) * 2;
    const int hl = lane >> 4;          // which head within the warp
    const int s  = lane & 15;          // state index
    const int h  = h0 + hl;

    const float a_hs = -__expf(f_log[h * S_ + s]);
    const float gd   = g[h];
    const float* zc_b = zc + (size_t)b * L_ * 64;
    const size_t base = (size_t)b * L_ * H_;

    float x = 0.f;

    // prefetch l=0
    float bc_n  = zc_b[32 + lane];
    float dtl_n = 0.f, ul_n = 0.f;
    if (lane < 2) {
        dtl_n = dt[base + h0 + lane];
        ul_n  = uc[base + h0 + lane];
    }

    for (int l = 0; l < L_; ++l) {
        const float bc  = bc_n;
        const float dtl = dtl_n;
        const float ul  = ul_n;
        if (l + 1 < L_) {               // software prefetch next step
            bc_n = zc_b[(size_t)(l + 1) * 64 + 32 + lane];
            if (lane < 2) {
                dtl_n = dt[base + (size_t)(l + 1) * H_ + h0 + lane];
                ul_n  = uc[base + (size_t)(l + 1) * H_ + h0 + lane];
            }
        }
        const float dtv = __shfl_sync(0xffffffffu, dtl, hl);
        const float uv  = __shfl_sync(0xffffffffu, ul,  hl);
        const float bmy = __shfl_sync(0xffffffffu, bc,  s);
        const float cmy = __shfl_sync(0xffffffffu, bc,  16 + s);

        const float aa = __expf(dtv * a_hs);
        x = aa * x + dtv * uv * bmy;

        float yp = x * cmy;
        yp += __shfl_xor_sync(0xffffffffu, yp, 8);
        yp += __shfl_xor_sync(0xffffffffu, yp, 4);
        yp += __shfl_xor_sync(0xffffffffu, yp, 2);
        yp += __shfl_xor_sync(0xffffffffu, yp, 1);

        if (s == 0) {
            const size_t o = base + (size_t)l * H_ + h;
            const float vv = v[o];
            const float sv = vv / (1.f + __expf(-vv));
            yv[o] = (yp + uv * gd) * sv;
        }
    }
}

// ---------------------------------------------------------------------------
// Launch
// ---------------------------------------------------------------------------
extern "C" void kernel_launch(void* const* d_in, const int* in_sizes, int n_in,
                              void* d_out, int out_size)
{
    const float* x      = (const float*)d_in[0];
    const float* ctx    = (const float*)d_in[1];
    const float* Wa     = (const float*)d_in[2];
    const float* ba     = (const float*)d_in[3];
    const float* conv_w = (const float*)d_in[4];
    const float* conv_b = (const float*)d_in[5];
    const float* Wc     = (const float*)d_in[6];
    const float* We     = (const float*)d_in[7];
    const float* be     = (const float*)d_in[8];
    const float* f_log  = (const float*)d_in[9];
    const float* g      = (const float*)d_in[10];
    const float* Wi     = (const float*)d_in[11];
    const float* bi     = (const float*)d_in[12];
    const float* ln_w   = (const float*)d_in[13];
    const float* ln_b   = (const float*)d_in[14];
    const float* Wgb    = (const float*)d_in[15];
    const float* bgb    = (const float*)d_in[16];
    const float* Wgc    = (const float*)d_in[17];
    const float* bgc    = (const float*)d_in[18];
    float* out = (float*)d_out;

    float *cln, *z, *p, *q, *u, *v, *uc, *zc, *dtb, *yv;
    cudaGetSymbolAddress((void**)&cln, g_cln);
    cudaGetSymbolAddress((void**)&z,   g_z);
    cudaGetSymbolAddress((void**)&p,   g_p);
    cudaGetSymbolAddress((void**)&q,   g_q);
    cudaGetSymbolAddress((void**)&u,   g_u);
    cudaGetSymbolAddress((void**)&v,   g_v);
    cudaGetSymbolAddress((void**)&uc,  g_uc);
    cudaGetSymbolAddress((void**)&zc,  g_zc);
    cudaGetSymbolAddress((void**)&dtb, g_dt);
    cudaGetSymbolAddress((void**)&yv,  g_yv);

    // 1. LayerNorm(ctx)
    ln_kernel<<<M_, 256>>>(ctx, ln_w, ln_b, cln);

    // 2. z = x @ Wa^T + ba                      [8192, 2048]
    gemm128<0><<<dim3(H2_ / 128, M_ / 128), 256>>>(x, D_, Wa, D_, ba, z, H2_, D_);

    // 3. p_raw = cln @ Wgb^T + bgb              [8192, 1024]
    gemm128<0><<<dim3(H_ / 128, M_ / 128), 256>>>(cln, D_, Wgb, D_, bgb, p, H_, D_);

    // 4. q = cln @ Wgc^T + bgc                  [8192, 1024]
    gemm128<0><<<dim3(H_ / 128, M_ / 128), 256>>>(cln, D_, Wgc, D_, bgc, q, H_, D_);

    // 5. u = z1*(1+sigmoid(p)), v = z2+q
    uv_kernel<<<(int)(((size_t)M_ * H_) / 256), 256>>>(z, p, q, u, v);

    // 6. uc = silu(causal depthwise conv3(u))
    conv_kernel<<<(int)(((size_t)M_ * H_) / 256), 256>>>(u, conv_w, conv_b, uc);

    // 7. zc = uc @ Wc^T                         [8192, 64]
    gemm64<<<dim3(1, M_ / 64), 256>>>(uc, H_, Wc, H_, zc, 64, H_);

    // 8. dt = softplus(zc[:, :R] @ We^T + be)   [8192, 1024]
    gemm128<1><<<dim3(H_ / 128, M_ / 128), 256>>>(zc, 64, We, R_, be, dtb, H_, R_);

    // 9. selective scan (fused skip + silu(v) gate) -> yv
    scan_kernel<<<(B_ * H_ / 2) / 8, 256>>>(uc, dtb, zc, v, f_log, g, yv);

    // 10. out = yv @ Wi^T + bi                  [8192, 512]
    gemm128<0><<<dim3(D_ / 128, M_ / 128), 256>>>(yv, H_, Wi, H_, bi, out, D_, H_);
}

// round 4
// speedup vs baseline: 1.4118x; 1.4118x over previous
#include <cuda_runtime.h>
#include <cstdint>
#include <math.h>

// ---------------------------------------------------------------------------
// Problem constants
// ---------------------------------------------------------------------------
constexpr int B_  = 4;
constexpr int L_  = 2048;
constexpr int D_  = 512;
constexpr int H_  = 1024;   // 2*D
constexpr int S_  = 16;
constexpr int M_  = B_ * L_;        // 8192 tokens
constexpr int H2_ = 2 * H_;         // 2048

// ---------------------------------------------------------------------------
// Scratch (device globals; no allocation allowed)
// ---------------------------------------------------------------------------
__device__ float g_cln[M_ * D_];
__device__ float g_z  [M_ * H2_];
__device__ float g_u  [M_ * H_];
__device__ float g_v  [M_ * H_];
__device__ float g_uc [M_ * H_];
__device__ float g_zc [M_ * 64];
__device__ float g_dt [M_ * H_];
__device__ float g_yv [M_ * H_];

// ---------------------------------------------------------------------------
// Helpers
// ---------------------------------------------------------------------------
__device__ __forceinline__ uint32_t smem_u32(const void* p) {
    uint32_t a;
    asm("{ .reg .u64 t; cvta.to.shared.u64 t, %1; cvt.u32.u64 %0, t; }"
        : "=r"(a) : "l"(p));
    return a;
}
__device__ __forceinline__ void cpa16(uint32_t dst, const void* src) {
    asm volatile("cp.async.cg.shared.global [%0], [%1], 16;"
                 :: "r"(dst), "l"(src));
}
__device__ __forceinline__ uint32_t cvt_tf32(float x) {
    uint32_t r;
    asm("cvt.rna.tf32.f32 %0, %1;" : "=r"(r) : "f"(x));
    return r;
}
__device__ __forceinline__ void mma_tf32_16x8x8(float c[4],
                                                const uint32_t a[4],
                                                const uint32_t b[2]) {
    asm volatile(
        "mma.sync.aligned.m16n8k8.row.col.f32.tf32.tf32.f32 "
        "{%0,%1,%2,%3}, {%4,%5,%6,%7}, {%8,%9}, {%0,%1,%2,%3};"
        : "+f"(c[0]), "+f"(c[1]), "+f"(c[2]), "+f"(c[3])
        : "r"(a[0]), "r"(a[1]), "r"(a[2]), "r"(a[3]),
          "r"(b[0]), "r"(b[1]));
}

// ---------------------------------------------------------------------------
// tf32 mma.sync GEMM:  C[m,n] = sum_k A[m,k] * W[n,k]  (+bias, +epilogue)
// Block 128 x (NT*32), 8 warps (2x4), warp tile 64 x (NT*8), BK = 8,
// double-buffered cp.async smem, padded row stride 12 floats (conflict-free).
// ACT: 0 identity  1 softplus  2 u-gate (z1*(1+sigmoid(.)))  3 v-add (z2+.)
// EX: extra input for ACT 2/3 (the z buffer, row stride H2_).
// ---------------------------------------------------------------------------
template<int ACT, int NT>
__global__ __launch_bounds__(256)
void mma_gemm(const float* __restrict__ A, int lda,
              const float* __restrict__ W, int ldw,
              const float* __restrict__ bias,
              const float* __restrict__ EX,
              float* __restrict__ C, int ldc, int K)
{
    constexpr int BN = NT * 32;               // 128 or 64
    __shared__ float As[2][128][12];
    __shared__ float Bs[2][BN][12];

    const int tid  = threadIdx.x;
    const int warp = tid >> 5, lane = tid & 31;
    const int gid  = lane >> 2, tig = lane & 3;
    const int wm   = warp & 1,  wn  = warp >> 1;
    const int m0   = blockIdx.y * 128;
    const int n0   = blockIdx.x * BN;
    const int mbase = wm * 64;
    const int nbase = wn * (NT * 8);

    float c[4][NT][4];
    #pragma unroll
    for (int i = 0; i < 4; i++)
        #pragma unroll
        for (int j = 0; j < NT; j++)
            #pragma unroll
            for (int q = 0; q < 4; q++) c[i][j][q] = 0.f;

    // gmem -> smem load assignment (16B per cp.async)
    const int arow = tid >> 1, acol = (tid & 1) * 4;
    const float* aptr = A + (size_t)(m0 + arow) * lda + acol;
    const bool  bload = (arow < BN);
    const float* bptr = bload ? (W + (size_t)(n0 + arow) * ldw + acol) : nullptr;

    const uint32_t adst0 = smem_u32(&As[0][arow][acol]);
    const uint32_t adst1 = smem_u32(&As[1][arow][acol]);
    const uint32_t bdst0 = bload ? smem_u32(&Bs[0][arow][acol]) : 0u;
    const uint32_t bdst1 = bload ? smem_u32(&Bs[1][arow][acol]) : 0u;

    const int nk = K >> 3;

    // prologue: stage 0
    cpa16(adst0, aptr);
    if (bload) cpa16(bdst0, bptr);
    asm volatile("cp.async.commit_group;" ::: "memory");

    for (int kt = 0; kt < nk; ++kt) {
        const int st = kt & 1;
        // issue next stage
        if (kt + 1 < nk) {
            const int ns = st ^ 1;
            cpa16(ns ? adst1 : adst0, aptr + (size_t)(kt + 1) * 8);
            if (bload) cpa16(ns ? bdst1 : bdst0, bptr + (size_t)(kt + 1) * 8);
        }
        asm volatile("cp.async.commit_group;" ::: "memory");
        asm volatile("cp.async.wait_group 1;" ::: "memory");
        __syncthreads();

        // fragments
        uint32_t af[4][4], bf[NT][2];
        #pragma unroll
        for (int ti = 0; ti < 4; ti++) {
            const int m = mbase + 16 * ti + gid;
            af[ti][0] = cvt_tf32(As[st][m    ][tig]);
            af[ti][1] = cvt_tf32(As[st][m + 8][tig]);
            af[ti][2] = cvt_tf32(As[st][m    ][tig + 4]);
            af[ti][3] = cvt_tf32(As[st][m + 8][tig + 4]);
        }
        #pragma unroll
        for (int tj = 0; tj < NT; tj++) {
            const int n = nbase + 8 * tj + gid;
            bf[tj][0] = cvt_tf32(Bs[st][n][tig]);
            bf[tj][1] = cvt_tf32(Bs[st][n][tig + 4]);
        }
        #pragma unroll
        for (int ti = 0; ti < 4; ti++)
            #pragma unroll
            for (int tj = 0; tj < NT; tj++)
                mma_tf32_16x8x8(c[ti][tj], af[ti], bf[tj]);

        __syncthreads();   // protect stage st before it is reloaded
    }

    // epilogue
    #pragma unroll
    for (int ti = 0; ti < 4; ti++) {
        #pragma unroll
        for (int half = 0; half < 2; half++) {
            const int row = m0 + mbase + 16 * ti + gid + half * 8;
            #pragma unroll
            for (int tj = 0; tj < NT; tj++) {
                const int col = n0 + nbase + 8 * tj + 2 * tig;
                float v0 = c[ti][tj][half * 2 + 0];
                float v1 = c[ti][tj][half * 2 + 1];
                if (bias) { v0 += bias[col]; v1 += bias[col + 1]; }
                if (ACT == 1) {
                    v0 = (v0 > 20.f) ? v0 : log1pf(__expf(v0));
                    v1 = (v1 > 20.f) ? v1 : log1pf(__expf(v1));
                } else if (ACT == 2) {
                    const float z10 = EX[(size_t)row * H2_ + col];
                    const float z11 = EX[(size_t)row * H2_ + col + 1];
                    v0 = z10 * (1.f + 1.f / (1.f + __expf(-v0)));
                    v1 = z11 * (1.f + 1.f / (1.f + __expf(-v1)));
                } else if (ACT == 3) {
                    v0 += EX[(size_t)row * H2_ + H_ + col];
                    v1 += EX[(size_t)row * H2_ + H_ + col + 1];
                }
                float2 r; r.x = v0; r.y = v1;
                *(float2*)(C + (size_t)row * ldc + col) = r;
            }
        }
    }
}

// ---------------------------------------------------------------------------
// LayerNorm over D=512, one block (256 threads) per token
// ---------------------------------------------------------------------------
__global__ void ln_kernel(const float* __restrict__ ctx,
                          const float* __restrict__ w,
                          const float* __restrict__ b,
                          float* __restrict__ out)
{
    __shared__ float red[32];
    const int m = blockIdx.x;
    const int t = threadIdx.x;
    const float* xr = ctx + (size_t)m * D_;
    float v0 = xr[t], v1 = xr[t + 256];

    float s = v0 + v1;
    #pragma unroll
    for (int o = 16; o; o >>= 1) s += __shfl_xor_sync(0xffffffffu, s, o);
    if ((t & 31) == 0) red[t >> 5] = s;
    __syncthreads();
    if (t < 32) {
        float r = (t < 8) ? red[t] : 0.f;
        #pragma unroll
        for (int o = 4; o; o >>= 1) r += __shfl_xor_sync(0xffffffffu, r, o);
        if (t == 0) red[0] = r;
    }
    __syncthreads();
    const float mu = red[0] * (1.f / D_);
    const float d0 = v0 - mu, d1 = v1 - mu;

    float sq = d0 * d0 + d1 * d1;
    #pragma unroll
    for (int o = 16; o; o >>= 1) sq += __shfl_xor_sync(0xffffffffu, sq, o);
    __syncthreads();
    if ((t & 31) == 0) red[t >> 5] = sq;
    __syncthreads();
    if (t < 32) {
        float r = (t < 8) ? red[t] : 0.f;
        #pragma unroll
        for (int o = 4; o; o >>= 1) r += __shfl_xor_sync(0xffffffffu, r, o);
        if (t == 0) red[0] = r;
    }
    __syncthreads();
    const float inv = rsqrtf(red[0] * (1.f / D_) + 1e-5f);

    float* orow = out + (size_t)m * D_;
    orow[t]       = d0 * inv * w[t]       + b[t];
    orow[t + 256] = d1 * inv * w[t + 256] + b[t + 256];
}

// ---------------------------------------------------------------------------
// Causal depthwise conv3 + SiLU
// ---------------------------------------------------------------------------
__global__ void conv_kernel(const float* __restrict__ u,
                            const float* __restrict__ cw,
                            const float* __restrict__ cb,
                            float* __restrict__ uc)
{
    const size_t idx = (size_t)blockIdx.x * blockDim.x + threadIdx.x;
    if (idx >= (size_t)M_ * H_) return;
    const int    h = (int)(idx % H_);
    const size_t m = idx / H_;
    const int    l = (int)(m % L_);
    const float x0  = u[idx];
    const float xm1 = (l >= 1) ? u[idx - H_]     : 0.f;
    const float xm2 = (l >= 2) ? u[idx - 2 * H_] : 0.f;
    const float r = cw[h * 3 + 0] * xm2 + cw[h * 3 + 1] * xm1
                  + cw[h * 3 + 2] * x0  + cb[h];
    uc[idx] = r / (1.f + __expf(-r));           // silu
}

// ---------------------------------------------------------------------------
// Selective scan. One warp = 2 heads of one batch; states in registers.
// ---------------------------------------------------------------------------
__global__ void scan_kernel(const float* __restrict__ uc,
                            const float* __restrict__ dt,
                            const float* __restrict__ zc,
                            const float* __restrict__ v,
                            const float* __restrict__ f_log,
                            const float* __restrict__ g,
                            float* __restrict__ yv)
{
    const int wid  = (int)((blockIdx.x * blockDim.x + threadIdx.x) >> 5);
    const int lane = threadIdx.x & 31;
    if (wid >= B_ * H_ / 2) return;
    const int b  = wid / (H_ / 2);
    const int h0 = (wid % (H_ / 2)) * 2;
    const int hl = lane >> 4;
    const int s  = lane & 15;
    const int h  = h0 + hl;

    const float a_hs = -__expf(f_log[h * S_ + s]);
    const float gd   = g[h];
    const float* zc_b = zc + (size_t)b * L_ * 64;
    const size_t base = (size_t)b * L_ * H_;

    float x = 0.f;

    float bc_n  = zc_b[32 + lane];
    float dtl_n = 0.f, ul_n = 0.f;
    if (lane < 2) {
        dtl_n = dt[base + h0 + lane];
        ul_n  = uc[base + h0 + lane];
    }

    for (int l = 0; l < L_; ++l) {
        const float bc  = bc_n;
        const float dtl = dtl_n;
        const float ul  = ul_n;
        if (l + 1 < L_) {
            bc_n = zc_b[(size_t)(l + 1) * 64 + 32 + lane];
            if (lane < 2) {
                dtl_n = dt[base + (size_t)(l + 1) * H_ + h0 + lane];
                ul_n  = uc[base + (size_t)(l + 1) * H_ + h0 + lane];
            }
        }
        const float dtv = __shfl_sync(0xffffffffu, dtl, hl);
        const float uv  = __shfl_sync(0xffffffffu, ul,  hl);
        const float bmy = __shfl_sync(0xffffffffu, bc,  s);
        const float cmy = __shfl_sync(0xffffffffu, bc,  16 + s);

        const float aa = __expf(dtv * a_hs);
        x = aa * x + dtv * uv * bmy;

        float yp = x * cmy;
        yp += __shfl_xor_sync(0xffffffffu, yp, 8);
        yp += __shfl_xor_sync(0xffffffffu, yp, 4);
        yp += __shfl_xor_sync(0xffffffffu, yp, 2);
        yp += __shfl_xor_sync(0xffffffffu, yp, 1);

        if (s == 0) {
            const size_t o = base + (size_t)l * H_ + h;
            const float vv = v[o];
            const float sv = vv / (1.f + __expf(-vv));
            yv[o] = (yp + uv * gd) * sv;
        }
    }
}

// ---------------------------------------------------------------------------
// Launch
// ---------------------------------------------------------------------------
extern "C" void kernel_launch(void* const* d_in, const int* in_sizes, int n_in,
                              void* d_out, int out_size)
{
    const float* x      = (const float*)d_in[0];
    const float* ctx    = (const float*)d_in[1];
    const float* Wa     = (const float*)d_in[2];
    const float* ba     = (const float*)d_in[3];
    const float* conv_w = (const float*)d_in[4];
    const float* conv_b = (const float*)d_in[5];
    const float* Wc     = (const float*)d_in[6];
    const float* We     = (const float*)d_in[7];
    const float* be     = (const float*)d_in[8];
    const float* f_log  = (const float*)d_in[9];
    const float* g      = (const float*)d_in[10];
    const float* Wi     = (const float*)d_in[11];
    const float* bi     = (const float*)d_in[12];
    const float* ln_w   = (const float*)d_in[13];
    const float* ln_b   = (const float*)d_in[14];
    const float* Wgb    = (const float*)d_in[15];
    const float* bgb    = (const float*)d_in[16];
    const float* Wgc    = (const float*)d_in[17];
    const float* bgc    = (const float*)d_in[18];
    float* out = (float*)d_out;

    float *cln, *z, *u, *v, *uc, *zc, *dtb, *yv;
    cudaGetSymbolAddress((void**)&cln, g_cln);
    cudaGetSymbolAddress((void**)&z,   g_z);
    cudaGetSymbolAddress((void**)&u,   g_u);
    cudaGetSymbolAddress((void**)&v,   g_v);
    cudaGetSymbolAddress((void**)&uc,  g_uc);
    cudaGetSymbolAddress((void**)&zc,  g_zc);
    cudaGetSymbolAddress((void**)&dtb, g_dt);
    cudaGetSymbolAddress((void**)&yv,  g_yv);

    // 1. LayerNorm(ctx)
    ln_kernel<<<M_, 256>>>(ctx, ln_w, ln_b, cln);

    // 2. z = x @ Wa^T + ba                      [8192, 2048]
    mma_gemm<0,4><<<dim3(H2_ / 128, M_ / 128), 256>>>(
        x, D_, Wa, D_, ba, nullptr, z, H2_, D_);

    // 3. u = z1 * (1 + sigmoid(cln @ Wgb^T + bgb))   (fused epilogue)
    mma_gemm<2,4><<<dim3(H_ / 128, M_ / 128), 256>>>(
        cln, D_, Wgb, D_, bgb, z, u, H_, D_);

    // 4. v = z2 + cln @ Wgc^T + bgc                  (fused epilogue)
    mma_gemm<3,4><<<dim3(H_ / 128, M_ / 128), 256>>>(
        cln, D_, Wgc, D_, bgc, z, v, H_, D_);

    // 5. uc = silu(causal depthwise conv3(u))
    conv_kernel<<<(int)(((size_t)M_ * H_) / 256), 256>>>(u, conv_w, conv_b, uc);

    // 6. zc = uc @ Wc^T                         [8192, 64]
    mma_gemm<0,2><<<dim3(1, M_ / 128), 256>>>(
        uc, H_, Wc, H_, nullptr, nullptr, zc, 64, H_);

    // 7. dt = softplus(zc[:, :R] @ We^T + be)   [8192, 1024]
    mma_gemm<1,4><<<dim3(H_ / 128, M_ / 128), 256>>>(
        zc, 64, We, 32, be, nullptr, dtb, H_, 32);

    // 8. selective scan (fused skip + silu(v) gate) -> yv
    scan_kernel<<<(B_ * H_ / 2) / 8, 256>>>(uc, dtb, zc, v, f_log, g, yv);

    // 9. out = yv @ Wi^T + bi                   [8192, 512]
    mma_gemm<0,4><<<dim3(D_ / 128, M_ / 128), 256>>>(
        yv, H_, Wi, H_, bi, nullptr, out, D_, H_);
}

// round 5
// speedup vs baseline: 3.3717x; 2.3883x over previous
#include <cuda_runtime.h>
#include <cstdint>
#include <math.h>

// ---------------------------------------------------------------------------
// Problem constants
// ---------------------------------------------------------------------------
constexpr int B_  = 4;
constexpr int L_  = 2048;
constexpr int D_  = 512;
constexpr int H_  = 1024;   // 2*D
constexpr int S_  = 16;
constexpr int M_  = B_ * L_;        // 8192 tokens
constexpr int H2_ = 2 * H_;         // 2048
constexpr int KSP_ = 4;             // split-K factor for the zc GEMM

// ---------------------------------------------------------------------------
// Scratch (device globals; no allocation allowed)
// ---------------------------------------------------------------------------
__device__ float g_cln[M_ * D_];
__device__ float g_z  [M_ * H2_];
__device__ float g_u  [M_ * H_];
__device__ float g_v  [M_ * H_];
__device__ float g_uc [M_ * H_];
__device__ float g_zcp[KSP_ * M_ * 64];   // split-K partials
__device__ float g_zc [M_ * 64];
__device__ float g_dt [M_ * H_];
__device__ float g_yv [M_ * H_];

// ---------------------------------------------------------------------------
// Helpers
// ---------------------------------------------------------------------------
__device__ __forceinline__ uint32_t smem_u32(const void* p) {
    uint32_t a;
    asm("{ .reg .u64 t; cvta.to.shared.u64 t, %1; cvt.u32.u64 %0, t; }"
        : "=r"(a) : "l"(p));
    return a;
}
__device__ __forceinline__ void cpa16(uint32_t dst, const void* src) {
    asm volatile("cp.async.cg.shared.global [%0], [%1], 16;"
                 :: "r"(dst), "l"(src));
}
__device__ __forceinline__ uint32_t cvt_tf32(float x) {
    uint32_t r;
    asm("cvt.rna.tf32.f32 %0, %1;" : "=r"(r) : "f"(x));
    return r;
}
__device__ __forceinline__ void mma_tf32_16x8x8(float c[4],
                                                const uint32_t a[4],
                                                const uint32_t b[2]) {
    asm volatile(
        "mma.sync.aligned.m16n8k8.row.col.f32.tf32.tf32.f32 "
        "{%0,%1,%2,%3}, {%4,%5,%6,%7}, {%8,%9}, {%0,%1,%2,%3};"
        : "+f"(c[0]), "+f"(c[1]), "+f"(c[2]), "+f"(c[3])
        : "r"(a[0]), "r"(a[1]), "r"(a[2]), "r"(a[3]),
          "r"(b[0]), "r"(b[1]));
}

// ---------------------------------------------------------------------------
// tf32 mma.sync GEMM:  C[m,n] = sum_k A[m,k] * W[n,k]  (+bias, +epilogue)
// Block 128 x (NT*32), 8 warps (2x4), warp tile 64 x (NT*8), BK = 8,
// 3-stage cp.async pipeline, ONE __syncthreads per k-tile,
// padded smem row stride 12 floats (conflict-free).
// ACT: 0 identity  1 softplus  2 u-gate (z1*(1+sigmoid(.)))  3 v-add (z2+.)
// KSPLIT > 1: blockIdx.x selects a K-chunk, n0 = 0, C += bx * M_ * ldc.
// ---------------------------------------------------------------------------
template<int ACT, int NT, int KSPLIT>
__global__ __launch_bounds__(256)
void mma_gemm(const float* __restrict__ A, int lda,
              const float* __restrict__ W, int ldw,
              const float* __restrict__ bias,
              const float* __restrict__ EX,
              float* __restrict__ C, int ldc, int K)
{
    constexpr int BN = NT * 32;               // 128 or 64
    __shared__ float As[3][128][12];
    __shared__ float Bs[3][BN][12];

    const int tid  = threadIdx.x;
    const int warp = tid >> 5, lane = tid & 31;
    const int gid  = lane >> 2, tig = lane & 3;
    const int wm   = warp & 1,  wn  = warp >> 1;
    const int m0   = blockIdx.y * 128;

    int n0, koff, keff;
    if (KSPLIT > 1) {
        n0   = 0;
        keff = K / KSPLIT;
        koff = blockIdx.x * keff;
        C   += (size_t)blockIdx.x * M_ * ldc;
    } else {
        n0   = blockIdx.x * BN;
        keff = K;
        koff = 0;
    }
    const int mbase = wm * 64;
    const int nbase = wn * (NT * 8);

    float c[4][NT][4];
    #pragma unroll
    for (int i = 0; i < 4; i++)
        #pragma unroll
        for (int j = 0; j < NT; j++)
            #pragma unroll
            for (int q = 0; q < 4; q++) c[i][j][q] = 0.f;

    // gmem -> smem load assignment (16B per cp.async)
    const int arow = tid >> 1, acol = (tid & 1) * 4;
    const float* aptr = A + (size_t)(m0 + arow) * lda + koff + acol;
    const bool  bload = (arow < BN);
    const float* bptr = bload ? (W + (size_t)(n0 + arow) * ldw + koff + acol)
                              : nullptr;

    uint32_t adst[3], bdst[3];
    #pragma unroll
    for (int t = 0; t < 3; t++) {
        adst[t] = smem_u32(&As[t][arow][acol]);
        bdst[t] = bload ? smem_u32(&Bs[t][arow][acol]) : 0u;
    }

    const int nk = keff >> 3;

    auto issue_stage = [&](int t) {
        if (t < nk) {
            cpa16(adst[t % 3], aptr + (size_t)t * 8);
            if (bload) cpa16(bdst[t % 3], bptr + (size_t)t * 8);
        }
        asm volatile("cp.async.commit_group;" ::: "memory");
    };

    issue_stage(0);
    issue_stage(1);

    for (int kt = 0; kt < nk; ++kt) {
        asm volatile("cp.async.wait_group 1;" ::: "memory");
        __syncthreads();
        issue_stage(kt + 2);

        const int st = kt % 3;
        uint32_t af[4][4], bf[NT][2];
        #pragma unroll
        for (int ti = 0; ti < 4; ti++) {
            const int m = mbase + 16 * ti + gid;
            af[ti][0] = cvt_tf32(As[st][m    ][tig]);
            af[ti][1] = cvt_tf32(As[st][m + 8][tig]);
            af[ti][2] = cvt_tf32(As[st][m    ][tig + 4]);
            af[ti][3] = cvt_tf32(As[st][m + 8][tig + 4]);
        }
        #pragma unroll
        for (int tj = 0; tj < NT; tj++) {
            const int n = nbase + 8 * tj + gid;
            bf[tj][0] = cvt_tf32(Bs[st][n][tig]);
            bf[tj][1] = cvt_tf32(Bs[st][n][tig + 4]);
        }
        #pragma unroll
        for (int ti = 0; ti < 4; ti++)
            #pragma unroll
            for (int tj = 0; tj < NT; tj++)
                mma_tf32_16x8x8(c[ti][tj], af[ti], bf[tj]);
    }

    // epilogue
    #pragma unroll
    for (int ti = 0; ti < 4; ti++) {
        #pragma unroll
        for (int half = 0; half < 2; half++) {
            const int row = m0 + mbase + 16 * ti + gid + half * 8;
            #pragma unroll
            for (int tj = 0; tj < NT; tj++) {
                const int col = n0 + nbase + 8 * tj + 2 * tig;
                float v0 = c[ti][tj][half * 2 + 0];
                float v1 = c[ti][tj][half * 2 + 1];
                if (bias) { v0 += bias[col]; v1 += bias[col + 1]; }
                if (ACT == 1) {
                    v0 = (v0 > 20.f) ? v0 : log1pf(__expf(v0));
                    v1 = (v1 > 20.f) ? v1 : log1pf(__expf(v1));
                } else if (ACT == 2) {
                    const float z10 = EX[(size_t)row * H2_ + col];
                    const float z11 = EX[(size_t)row * H2_ + col + 1];
                    v0 = z10 * (1.f + 1.f / (1.f + __expf(-v0)));
                    v1 = z11 * (1.f + 1.f / (1.f + __expf(-v1)));
                } else if (ACT == 3) {
                    v0 += EX[(size_t)row * H2_ + H_ + col];
                    v1 += EX[(size_t)row * H2_ + H_ + col + 1];
                }
                float2 r; r.x = v0; r.y = v1;
                *(float2*)(C + (size_t)row * ldc + col) = r;
            }
        }
    }
}

// ---------------------------------------------------------------------------
// Reduce split-K partials:  zc = sum over KSP_ chunks of g_zcp
// ---------------------------------------------------------------------------
__global__ void zc_reduce(const float* __restrict__ zp,
                          float* __restrict__ zc)
{
    const int idx = blockIdx.x * blockDim.x + threadIdx.x;   // float4 index
    if (idx >= M_ * 64 / 4) return;
    const float4* p0 = (const float4*)zp + idx;
    float4 a = p0[0];
    #pragma unroll
    for (int j = 1; j < KSP_; j++) {
        const float4 bq = p0[(size_t)j * (M_ * 64 / 4)];
        a.x += bq.x; a.y += bq.y; a.z += bq.z; a.w += bq.w;
    }
    ((float4*)zc)[idx] = a;
}

// ---------------------------------------------------------------------------
// LayerNorm over D=512, one block (256 threads) per token
// ---------------------------------------------------------------------------
__global__ void ln_kernel(const float* __restrict__ ctx,
                          const float* __restrict__ w,
                          const float* __restrict__ b,
                          float* __restrict__ out)
{
    __shared__ float red[32];
    const int m = blockIdx.x;
    const int t = threadIdx.x;
    const float* xr = ctx + (size_t)m * D_;
    float v0 = xr[t], v1 = xr[t + 256];

    float s = v0 + v1;
    #pragma unroll
    for (int o = 16; o; o >>= 1) s += __shfl_xor_sync(0xffffffffu, s, o);
    if ((t & 31) == 0) red[t >> 5] = s;
    __syncthreads();
    if (t < 32) {
        float r = (t < 8) ? red[t] : 0.f;
        #pragma unroll
        for (int o = 4; o; o >>= 1) r += __shfl_xor_sync(0xffffffffu, r, o);
        if (t == 0) red[0] = r;
    }
    __syncthreads();
    const float mu = red[0] * (1.f / D_);
    const float d0 = v0 - mu, d1 = v1 - mu;

    float sq = d0 * d0 + d1 * d1;
    #pragma unroll
    for (int o = 16; o; o >>= 1) sq += __shfl_xor_sync(0xffffffffu, sq, o);
    __syncthreads();
    if ((t & 31) == 0) red[t >> 5] = sq;
    __syncthreads();
    if (t < 32) {
        float r = (t < 8) ? red[t] : 0.f;
        #pragma unroll
        for (int o = 4; o; o >>= 1) r += __shfl_xor_sync(0xffffffffu, r, o);
        if (t == 0) red[0] = r;
    }
    __syncthreads();
    const float inv = rsqrtf(red[0] * (1.f / D_) + 1e-5f);

    float* orow = out + (size_t)m * D_;
    orow[t]       = d0 * inv * w[t]       + b[t];
    orow[t + 256] = d1 * inv * w[t + 256] + b[t + 256];
}

// ---------------------------------------------------------------------------
// Causal depthwise conv3 + SiLU
// ---------------------------------------------------------------------------
__global__ void conv_kernel(const float* __restrict__ u,
                            const float* __restrict__ cw,
                            const float* __restrict__ cb,
                            float* __restrict__ uc)
{
    const size_t idx = (size_t)blockIdx.x * blockDim.x + threadIdx.x;
    if (idx >= (size_t)M_ * H_) return;
    const int    h = (int)(idx % H_);
    const size_t m = idx / H_;
    const int    l = (int)(m % L_);
    const float x0  = u[idx];
    const float xm1 = (l >= 1) ? u[idx - H_]     : 0.f;
    const float xm2 = (l >= 2) ? u[idx - 2 * H_] : 0.f;
    const float r = cw[h * 3 + 0] * xm2 + cw[h * 3 + 1] * xm1
                  + cw[h * 3 + 2] * x0  + cb[h];
    uc[idx] = r / (1.f + __expf(-r));           // silu
}

// ---------------------------------------------------------------------------
// Selective scan, chunked (CH=16 steps per chunk).
// One warp = 2 heads of one batch.
//   scan roles : lane = (hl = lane>>4, s = lane&15)  state index
//   load roles : lane = (hl, jj = lane&15)           time-step within chunk
// Per chunk each lane loads 16 zc values + its own dt/uc/v element
// (19 independent loads, double-buffered one chunk ahead), the 16 inner
// steps are pure register/shuffle math, and stores happen once per chunk.
// ---------------------------------------------------------------------------
__global__ void scan_kernel(const float* __restrict__ uc,
                            const float* __restrict__ dt,
                            const float* __restrict__ zc,
                            const float* __restrict__ v,
                            const float* __restrict__ f_log,
                            const float* __restrict__ g,
                            float* __restrict__ yv)
{
    const int wid  = (int)((blockIdx.x * blockDim.x + threadIdx.x) >> 5);
    const int lane = threadIdx.x & 31;
    if (wid >= B_ * H_ / 2) return;
    const int b  = wid / (H_ / 2);
    const int h0 = (wid % (H_ / 2)) * 2;
    const int hl = lane >> 4;
    const int s  = lane & 15;          // doubles as jj (time-step in chunk)
    const int h  = h0 + hl;

    const float a_hs = -__expf(f_log[h * S_ + s]);
    const float gd   = g[h];
    const float* zcb  = zc + (size_t)b * L_ * 64;
    const size_t baseH = (size_t)b * L_ * H_ + h;   // (l=0, own head)

    float bc0[16], dt0, uc0, vv0;
    {
        #pragma unroll
        for (int j = 0; j < 16; j++)
            bc0[j] = zcb[(size_t)j * 64 + 32 + lane];
        const size_t o = baseH + (size_t)s * H_;
        dt0 = dt[o]; uc0 = uc[o]; vv0 = v[o];
    }

    float x = 0.f;

    for (int l0 = 0; l0 < L_; l0 += 16) {
        float bc1[16], dt1, uc1, vv1;
        if (l0 + 16 < L_) {
            #pragma unroll
            for (int j = 0; j < 16; j++)
                bc1[j] = zcb[(size_t)(l0 + 16 + j) * 64 + 32 + lane];
            const size_t o = baseH + (size_t)(l0 + 16 + s) * H_;
            dt1 = dt[o]; uc1 = uc[o]; vv1 = v[o];
        } else { dt1 = uc1 = vv1 = 0.f; }

        float outv = 0.f;
        #pragma unroll
        for (int j = 0; j < 16; j++) {
            const float dtq = __shfl_sync(0xffffffffu, dt0, hl * 16 + j);
            const float uq  = __shfl_sync(0xffffffffu, uc0, hl * 16 + j);
            const float bm  = __shfl_sync(0xffffffffu, bc0[j], s);
            const float cm  = __shfl_sync(0xffffffffu, bc0[j], 16 + s);

            const float aa = __expf(dtq * a_hs);
            x = fmaf(aa, x, dtq * uq * bm);

            float yp = x * cm;
            yp += __shfl_xor_sync(0xffffffffu, yp, 8);
            yp += __shfl_xor_sync(0xffffffffu, yp, 4);
            yp += __shfl_xor_sync(0xffffffffu, yp, 2);
            yp += __shfl_xor_sync(0xffffffffu, yp, 1);
            if (s == j) outv = yp;
        }

        const float sv = vv0 / (1.f + __expf(-vv0));
        yv[baseH + (size_t)(l0 + s) * H_] = (outv + uc0 * gd) * sv;

        #pragma unroll
        for (int j = 0; j < 16; j++) bc0[j] = bc1[j];
        dt0 = dt1; uc0 = uc1; vv0 = vv1;
    }
}

// ---------------------------------------------------------------------------
// Launch
// ---------------------------------------------------------------------------
extern "C" void kernel_launch(void* const* d_in, const int* in_sizes, int n_in,
                              void* d_out, int out_size)
{
    const float* x      = (const float*)d_in[0];
    const float* ctx    = (const float*)d_in[1];
    const float* Wa     = (const float*)d_in[2];
    const float* ba     = (const float*)d_in[3];
    const float* conv_w = (const float*)d_in[4];
    const float* conv_b = (const float*)d_in[5];
    const float* Wc     = (const float*)d_in[6];
    const float* We     = (const float*)d_in[7];
    const float* be     = (const float*)d_in[8];
    const float* f_log  = (const float*)d_in[9];
    const float* g      = (const float*)d_in[10];
    const float* Wi     = (const float*)d_in[11];
    const float* bi     = (const float*)d_in[12];
    const float* ln_w   = (const float*)d_in[13];
    const float* ln_b   = (const float*)d_in[14];
    const float* Wgb    = (const float*)d_in[15];
    const float* bgb    = (const float*)d_in[16];
    const float* Wgc    = (const float*)d_in[17];
    const float* bgc    = (const float*)d_in[18];
    float* out = (float*)d_out;

    float *cln, *z, *u, *v, *uc, *zcp, *zcb, *dtb, *yv;
    cudaGetSymbolAddress((void**)&cln, g_cln);
    cudaGetSymbolAddress((void**)&z,   g_z);
    cudaGetSymbolAddress((void**)&u,   g_u);
    cudaGetSymbolAddress((void**)&v,   g_v);
    cudaGetSymbolAddress((void**)&uc,  g_uc);
    cudaGetSymbolAddress((void**)&zcp, g_zcp);
    cudaGetSymbolAddress((void**)&zcb, g_zc);
    cudaGetSymbolAddress((void**)&dtb, g_dt);
    cudaGetSymbolAddress((void**)&yv,  g_yv);

    // 1. LayerNorm(ctx)
    ln_kernel<<<M_, 256>>>(ctx, ln_w, ln_b, cln);

    // 2. z = x @ Wa^T + ba                      [8192, 2048]
    mma_gemm<0,4,1><<<dim3(H2_ / 128, M_ / 128), 256>>>(
        x, D_, Wa, D_, ba, nullptr, z, H2_, D_);

    // 3. u = z1 * (1 + sigmoid(cln @ Wgb^T + bgb))
    mma_gemm<2,4,1><<<dim3(H_ / 128, M_ / 128), 256>>>(
        cln, D_, Wgb, D_, bgb, z, u, H_, D_);

    // 4. v = z2 + cln @ Wgc^T + bgc
    mma_gemm<3,4,1><<<dim3(H_ / 128, M_ / 128), 256>>>(
        cln, D_, Wgc, D_, bgc, z, v, H_, D_);

    // 5. uc = silu(causal depthwise conv3(u))
    conv_kernel<<<(int)(((size_t)M_ * H_) / 256), 256>>>(u, conv_w, conv_b, uc);

    // 6. zc = uc @ Wc^T  (split-K over 4 chunks, then reduce)
    mma_gemm<0,2,KSP_><<<dim3(KSP_, M_ / 128), 256>>>(
        uc, H_, Wc, H_, nullptr, nullptr, zcp, 64, H_);
    zc_reduce<<<(M_ * 64 / 4 + 255) / 256, 256>>>(zcp, zcb);

    // 7. dt = softplus(zc[:, :R] @ We^T + be)   [8192, 1024]
    mma_gemm<1,4,1><<<dim3(H_ / 128, M_ / 128), 256>>>(
        zcb, 64, We, 32, be, nullptr, dtb, H_, 32);

    // 8. selective scan (fused skip + silu(v) gate) -> yv
    scan_kernel<<<(B_ * H_ / 2) / 8, 256>>>(uc, dtb, zcb, v, f_log, g, yv);

    // 9. out = yv @ Wi^T + bi                   [8192, 512]
    mma_gemm<0,4,1><<<dim3(D_ / 128, M_ / 128), 256>>>(
        yv, H_, Wi, H_, bi, nullptr, out, D_, H_);
}